// round 7
// baseline (speedup 1.0000x reference)
#include <cuda_runtime.h>
#include <cuda_fp16.h>
#include <cstdint>

#define NN 100000
#define NE 1000000
#define NGR 512
#define HTILES 782   // (NN+127)/128

// ---------------- scratch ----------------
__device__ float g_Win[NN];       // sum of incoming edge weights (atomic, fill)
__device__ float g_atts[NN];      // src-side attention sum (atomic, edge)
__device__ float g_attd[NN];      // dst-side attention sum (atomic, fill)
__device__ int   g_degs[NN];      // src-side degree (atomic, edge)
__device__ int   g_cnt[NN];       // in-degree (CSR row counts)
__device__ int   g_rs[NN];        // CSR row start
__device__ int   g_cur[NN];       // CSR fill cursor
__device__ int   g_bsum[128];     // chained-scan flags
__device__ int   g_tick;
__device__ float2 g_ce[NE];       // CSR: {src_as_bits, w}
__device__ __half g_hh[NN * 64];
__device__ __half g_Ah[NN * 64];
__device__ __half g_Dh[NN * 64];
__device__ unsigned g_count = 0;  // grid barrier
__device__ unsigned g_gen = 0;

__device__ __forceinline__ uint32_t f2tf32(float f) {
    uint32_t o;
    asm("cvt.rna.tf32.f32 %0, %1;" : "=r"(o) : "f"(f));
    return o;
}

__device__ __forceinline__ void gridbar(unsigned nb) {
    __syncthreads();
    if (threadIdx.x == 0) {
        __threadfence();
        unsigned gen = atomicAdd(&g_gen, 0u);
        if (atomicAdd(&g_count, 1u) == nb - 1u) {
            atomicExch(&g_count, 0u);
            __threadfence();
            atomicAdd(&g_gen, 1u);
        } else {
            while (atomicAdd(&g_gen, 0u) == gen) {}
        }
    }
    __syncthreads();
}

// ---------------- init: zero scratch + node embedding (h fp16) ----------------
__global__ void k_init(const float* __restrict__ x, const float* __restrict__ w,
                       const float* __restrict__ b) {
    int gid = blockIdx.x * 256 + threadIdx.x;
    if (gid < NN) {
        g_atts[gid] = 0.f; g_attd[gid] = 0.f; g_Win[gid] = 0.f;
        g_degs[gid] = 0; g_cnt[gid] = 0;
    }
    if (gid < 128) g_bsum[gid] = 0;
    if (gid == 0) g_tick = 0;
    if (gid < NN * 32) {
        int i = gid >> 5, c = (gid & 31) * 2;
        float x0 = x[i * 4], x1 = x[i * 4 + 1], x2 = x[i * 4 + 2], x3 = x[i * 4 + 3];
        float h0 = b[c]     + x0 * w[c]     + x1 * w[64 + c]     + x2 * w[128 + c]     + x3 * w[192 + c];
        float h1 = b[c + 1] + x0 * w[c + 1] + x1 * w[64 + c + 1] + x2 * w[128 + c + 1] + x3 * w[192 + c + 1];
        *(__half2*)&g_hh[i * 64 + c] = __floats2half2_rn(h0, h1);
    }
}

// ---------------- edge pass: dst histogram + src-side atomics ----------------
__global__ void k_edge(const int* __restrict__ src, const int* __restrict__ dst,
                       const float* __restrict__ atten) {
    int e4 = blockIdx.x * 256 + threadIdx.x;
    if (e4 * 4 >= NE) return;
    int4 s = *(const int4*)&src[e4 * 4];
    int4 d = *(const int4*)&dst[e4 * 4];
    float4 at = *(const float4*)&atten[e4 * 4];
    atomicAdd(&g_cnt[d.x], 1); atomicAdd(&g_cnt[d.y], 1);
    atomicAdd(&g_cnt[d.z], 1); atomicAdd(&g_cnt[d.w], 1);
    atomicAdd(&g_atts[s.x], at.x); atomicAdd(&g_atts[s.y], at.y);
    atomicAdd(&g_atts[s.z], at.z); atomicAdd(&g_atts[s.w], at.w);
    atomicAdd(&g_degs[s.x], 1); atomicAdd(&g_degs[s.y], 1);
    atomicAdd(&g_degs[s.z], 1); atomicAdd(&g_degs[s.w], 1);
}

// ---------------- single-pass chained exclusive scan ----------------
__global__ void k_scan() {
    __shared__ int sm_t, sm_prev, wsum[8];
    int tid = threadIdx.x;
    if (tid == 0) sm_t = atomicAdd(&g_tick, 1);
    __syncthreads();
    int t = sm_t;
    int base = t * 1024 + tid * 4;
    int v0 = 0, v1 = 0, v2 = 0, v3 = 0;
    if (base + 3 < NN) {
        int4 q = *(const int4*)&g_cnt[base];
        v0 = q.x; v1 = q.y; v2 = q.z; v3 = q.w;
    } else {
        if (base < NN)     v0 = g_cnt[base];
        if (base + 1 < NN) v1 = g_cnt[base + 1];
        if (base + 2 < NN) v2 = g_cnt[base + 2];
        if (base + 3 < NN) v3 = g_cnt[base + 3];
    }
    int sloc = v0 + v1 + v2 + v3;
    int x = sloc;
#pragma unroll
    for (int o = 1; o < 32; o <<= 1) {
        int y = __shfl_up_sync(0xffffffffu, x, o);
        if ((tid & 31) >= o) x += y;
    }
    if ((tid & 31) == 31) wsum[tid >> 5] = x;
    __syncthreads();
    if (tid < 8) {
        int y = wsum[tid];
#pragma unroll
        for (int o = 1; o < 8; o <<= 1) {
            int z = __shfl_up_sync(0xffu, y, o);
            if (tid >= o) y += z;
        }
        wsum[tid] = y;
    }
    __syncthreads();
    int woff = (tid >= 32) ? wsum[(tid >> 5) - 1] : 0;
    int excl = x - sloc + woff;
    int total = wsum[7];
    if (tid == 0) {
        int prev = 0;
        if (t > 0) {
            int v;
            while ((v = atomicAdd(&g_bsum[t - 1], 0)) == 0) {}
            prev = v - 1;
        }
        atomicExch(&g_bsum[t], prev + total + 1);
        sm_prev = prev;
    }
    __syncthreads();
    int off = sm_prev + excl;
    if (base < NN)     { g_rs[base]     = off;                g_cur[base]     = off; }
    if (base + 1 < NN) { g_rs[base + 1] = off + v0;           g_cur[base + 1] = off + v0; }
    if (base + 2 < NN) { g_rs[base + 2] = off + v0 + v1;      g_cur[base + 2] = off + v0 + v1; }
    if (base + 3 < NN) { g_rs[base + 3] = off + v0 + v1 + v2; g_cur[base + 3] = off + v0 + v1 + v2; }
}

// ---------------- CSR fill + dst-side atomics (4 edges/thread) ----------------
__global__ void k_fill(const int* __restrict__ src, const int* __restrict__ dst,
                       const float* __restrict__ attr, const float* __restrict__ atten) {
    int e4 = blockIdx.x * 256 + threadIdx.x;
    if (e4 * 4 >= NE) return;
    int4 s = *(const int4*)&src[e4 * 4];
    int4 d = *(const int4*)&dst[e4 * 4];
    float4 ar = *(const float4*)&attr[e4 * 4];
    float4 at = *(const float4*)&atten[e4 * 4];
    int p0 = atomicAdd(&g_cur[d.x], 1);
    int p1 = atomicAdd(&g_cur[d.y], 1);
    int p2 = atomicAdd(&g_cur[d.z], 1);
    int p3 = atomicAdd(&g_cur[d.w], 1);
    float w0 = ar.x * at.x, w1 = ar.y * at.y, w2 = ar.z * at.z, w3 = ar.w * at.w;
    g_ce[p0] = make_float2(__int_as_float(s.x), w0);
    g_ce[p1] = make_float2(__int_as_float(s.y), w1);
    g_ce[p2] = make_float2(__int_as_float(s.z), w2);
    g_ce[p3] = make_float2(__int_as_float(s.w), w3);
    atomicAdd(&g_Win[d.x], w0); atomicAdd(&g_Win[d.y], w1);
    atomicAdd(&g_Win[d.z], w2); atomicAdd(&g_Win[d.w], w3);
    atomicAdd(&g_attd[d.x], at.x); atomicAdd(&g_attd[d.y], at.y);
    atomicAdd(&g_attd[d.z], at.z); atomicAdd(&g_attd[d.w], at.w);
}

// ---------------- persistent mega kernel: 3 x (GEMM, gather) + pool/MLP -------
__global__ void __launch_bounds__(256, 2) k_mega(
    const float* __restrict__ l1w, const float* __restrict__ l1b,
    const float* __restrict__ l2w, const float* __restrict__ l3w,
    const float* __restrict__ l3b, const int* __restrict__ batch,
    const float* __restrict__ f1w, const float* __restrict__ f1b,
    const float* __restrict__ f2w, const float* __restrict__ f2b,
    float* __restrict__ out, int nbi) {
    extern __shared__ float sm[];
    float* sh_h = sm;              // [128][68] tf32 words
    float* sh_w = sm + 128 * 68;   // [64][200]
    int tid = threadIdx.x;
    int bid = blockIdx.x;
    unsigned nb = (unsigned)nbi;

    int w = tid >> 5, lane = tid & 31;
    int rowG = w & 3, colH = w >> 2;
    int gid = lane >> 2, tid4 = lane & 3;

    for (int l = 0; l < 3; l++) {
        const float* W1 = l1w + l * 4096;
        const float* W2 = l2w + l * 4096;
        const float* W3 = l3w + l * 4096;
        const float* b1 = l1b + l * 64;
        const float* b3 = l3b + l * 64;

        // load the 3 weight matrices once per layer
        for (int i = tid; i < 3072; i += 256) {
            int row = i / 48;
            int q = i % 48;
            int m = q >> 4, c4 = (q & 15) << 2;
            const float* Wm = (m == 0) ? W1 : ((m == 1) ? W2 : W3);
            float4 v = *(const float4*)&Wm[row * 64 + c4];
            uint32_t* p = (uint32_t*)&sh_w[row * 200 + m * 64 + c4];
            p[0] = f2tf32(v.x); p[1] = f2tf32(v.y); p[2] = f2tf32(v.z); p[3] = f2tf32(v.w);
        }
        __syncthreads();

        for (int tile = bid; tile < HTILES; tile += nbi) {
            int nbase = tile * 128;
            for (int i = tid; i < 1024; i += 256) {
                int node = i >> 3, k8 = (i & 7) << 3;
                int gn = nbase + node;
                uint4 v = make_uint4(0u, 0u, 0u, 0u);
                if (gn < NN) v = *(const uint4*)&g_hh[gn * 64 + k8];
                __half2* hv = (__half2*)&v;
                uint32_t* p = (uint32_t*)&sh_h[node * 68 + k8];
#pragma unroll
                for (int j = 0; j < 4; j++) {
                    float2 f = __half22float2(hv[j]);
                    p[2 * j] = f2tf32(f.x); p[2 * j + 1] = f2tf32(f.y);
                }
            }
            __syncthreads();

            float acc[24][4];
#pragma unroll
            for (int t = 0; t < 24; t++) {
                acc[t][0] = 0.f; acc[t][1] = 0.f; acc[t][2] = 0.f; acc[t][3] = 0.f;
            }
            const uint32_t* hp = (const uint32_t*)(sh_h + rowG * 32 * 68);
            const uint32_t* wp = (const uint32_t*)sh_w;
#pragma unroll
            for (int kt = 0; kt < 8; kt++) {
                int k0 = kt * 8;
                uint32_t a[2][4];
#pragma unroll
                for (int rt = 0; rt < 2; rt++) {
                    const uint32_t* hq = hp + rt * 16 * 68;
                    a[rt][0] = hq[gid * 68 + k0 + tid4];
                    a[rt][1] = hq[(gid + 8) * 68 + k0 + tid4];
                    a[rt][2] = hq[gid * 68 + k0 + tid4 + 4];
                    a[rt][3] = hq[(gid + 8) * 68 + k0 + tid4 + 4];
                }
#pragma unroll
                for (int m = 0; m < 3; m++) {
#pragma unroll
                    for (int tt = 0; tt < 4; tt++) {
                        int nbo = m * 64 + colH * 32 + tt * 8;
                        uint32_t bb0 = wp[(k0 + tid4) * 200 + nbo + gid];
                        uint32_t bb1 = wp[(k0 + tid4 + 4) * 200 + nbo + gid];
#pragma unroll
                        for (int rt = 0; rt < 2; rt++) {
                            float* c = acc[rt * 12 + m * 4 + tt];
                            asm volatile(
                                "mma.sync.aligned.m16n8k8.row.col.f32.tf32.tf32.f32 "
                                "{%0,%1,%2,%3}, {%4,%5,%6,%7}, {%8,%9}, {%0,%1,%2,%3};"
                                : "+f"(c[0]), "+f"(c[1]), "+f"(c[2]), "+f"(c[3])
                                : "r"(a[rt][0]), "r"(a[rt][1]), "r"(a[rt][2]), "r"(a[rt][3]),
                                  "r"(bb0), "r"(bb1));
                        }
                    }
                }
            }
#pragma unroll
            for (int rt = 0; rt < 2; rt++) {
                int r1 = nbase + rowG * 32 + rt * 16 + gid;
                int r2 = r1 + 8;
                float win1 = (r1 < NN) ? g_Win[r1] : 0.f;
                float win2 = (r2 < NN) ? g_Win[r2] : 0.f;
#pragma unroll
                for (int tt = 0; tt < 4; tt++) {
                    int c = colH * 32 + tt * 8 + tid4 * 2;
                    float2 b1v = *(const float2*)&b1[c];
                    float2 b3v = *(const float2*)&b3[c];
                    float* aW1 = acc[rt * 12 + tt];
                    float* aW2 = acc[rt * 12 + 4 + tt];
                    float* aW3 = acc[rt * 12 + 8 + tt];
                    if (r1 < NN) {
                        *(__half2*)&g_Ah[r1 * 64 + c] =
                            __floats2half2_rn(aW1[0] + b1v.x, aW1[1] + b1v.y);
                        *(__half2*)&g_Dh[r1 * 64 + c] =
                            __floats2half2_rn(aW3[0] + b3v.x - win1 * aW2[0],
                                              aW3[1] + b3v.y - win1 * aW2[1]);
                    }
                    if (r2 < NN) {
                        *(__half2*)&g_Ah[r2 * 64 + c] =
                            __floats2half2_rn(aW1[2] + b1v.x, aW1[3] + b1v.y);
                        *(__half2*)&g_Dh[r2 * 64 + c] =
                            __floats2half2_rn(aW3[2] + b3v.x - win2 * aW2[2],
                                              aW3[3] + b3v.y - win2 * aW2[3]);
                    }
                }
            }
            __syncthreads();
        }
        gridbar(nb);

        // gather phase: warp per node, block-stride
        int loff = lane * 2;
        for (int node = bid * 8 + w; node < NN; node += nbi * 8) {
            int s = g_rs[node];
            int e = s + g_cnt[node];
            float ax0 = 0.f, ay0 = 0.f, ax1 = 0.f, ay1 = 0.f;
            for (int base = s; base < e; base += 32) {
                int idx = base + lane;
                float2 ce = make_float2(0.f, 0.f);
                if (idx < e) ce = g_ce[idx];
                int sn = __float_as_int(ce.x);
                float wv = ce.y;
                int m = min(32, e - base);
                int mr = (m + 3) & ~3;
                for (int j = 0; j < mr; j += 4) {
                    int s0 = __shfl_sync(0xffffffffu, sn, j);
                    int s1 = __shfl_sync(0xffffffffu, sn, j + 1);
                    int s2 = __shfl_sync(0xffffffffu, sn, j + 2);
                    int s3 = __shfl_sync(0xffffffffu, sn, j + 3);
                    float w0 = __shfl_sync(0xffffffffu, wv, j);
                    float w1 = __shfl_sync(0xffffffffu, wv, j + 1);
                    float w2 = __shfl_sync(0xffffffffu, wv, j + 2);
                    float w3 = __shfl_sync(0xffffffffu, wv, j + 3);
                    float2 v0 = __half22float2(__ldg((const __half2*)&g_Ah[s0 * 64 + loff]));
                    float2 v1 = __half22float2(__ldg((const __half2*)&g_Ah[s1 * 64 + loff]));
                    float2 v2 = __half22float2(__ldg((const __half2*)&g_Ah[s2 * 64 + loff]));
                    float2 v3 = __half22float2(__ldg((const __half2*)&g_Ah[s3 * 64 + loff]));
                    ax0 = fmaf(w0, v0.x, ax0); ay0 = fmaf(w0, v0.y, ay0);
                    ax1 = fmaf(w1, v1.x, ax1); ay1 = fmaf(w1, v1.y, ay1);
                    ax0 = fmaf(w2, v2.x, ax0); ay0 = fmaf(w2, v2.y, ay0);
                    ax1 = fmaf(w3, v3.x, ax1); ay1 = fmaf(w3, v3.y, ay1);
                }
            }
            float2 dv = __half22float2(*(const __half2*)&g_Dh[node * 64 + loff]);
            *(__half2*)&g_hh[node * 64 + loff] =
                __floats2half2_rn(fmaxf(ax0 + ax1 + dv.x, 0.f), fmaxf(ay0 + ay1 + dv.y, 0.f));
        }
        gridbar(nb);
    }

    // pool + MLP phase: block-stride over graphs, 256 threads
    int* se = (int*)sm;
    float* sacc = sm + 2;
    float* satt = sm + 2 + 256;
    float* sx = sm + 2 + 512;
    float* shh = sm + 2 + 576;
    for (int g = bid; g < NGR; g += nbi) {
        if (tid < 2) {
            int key = g + tid;
            int lo = 0, hi = NN;
            while (lo < hi) {
                int mid = (lo + hi) >> 1;
                if (batch[mid] < key) lo = mid + 1; else hi = mid;
            }
            se[tid] = lo;
        }
        __syncthreads();
        int s = se[0], e = se[1];
        int c = tid & 63, part = tid >> 6;
        float acc = 0.f, att = 0.f;
        for (int i = s + part; i < e; i += 4) {
            int dg = g_degs[i] + g_cnt[i];
            float na = (g_atts[i] + g_attd[i]) / ((dg == 0) ? 1.f : (float)dg);
            acc = fmaf(__half2float(g_hh[i * 64 + c]), na, acc);
            att += na;
        }
        sacc[tid] = acc; satt[tid] = att;
        __syncthreads();
        if (tid < 64) {
            float a = sacc[tid] + sacc[tid + 64] + sacc[tid + 128] + sacc[tid + 192];
            float at = satt[0] + satt[64] + satt[128] + satt[192];
            float cnt = (float)(e - s);
            float gat = (at == 0.f) ? 1.f : at;
            float scale = cnt / (gat * fmaxf(cnt, 1.f));
            sx[tid] = a * scale;
        }
        __syncthreads();
        if (tid < 128) {
            float a = f1b[tid];
#pragma unroll 8
            for (int k = 0; k < 64; k++) a = fmaf(sx[k], f1w[k * 128 + tid], a);
            shh[tid] = fmaxf(a, 0.f);
        }
        __syncthreads();
        if (tid < 3) {
            float o = f2b[tid];
            for (int j = 0; j < 128; j++) o = fmaf(shh[j], f2w[j * 3 + tid], o);
            out[g * 3 + tid] = o;
        }
        __syncthreads();
    }
}

// ---------------- launch ----------------
extern "C" void kernel_launch(void* const* d_in, const int* in_sizes, int n_in,
                              void* d_out, int out_size) {
    const float* x     = (const float*)d_in[0];
    const int*   ei    = (const int*)d_in[1];
    const int*   batch = (const int*)d_in[2];
    const float* eattr = (const float*)d_in[3];
    const float* eatt  = (const float*)d_in[4];
    const float* embw  = (const float*)d_in[5];
    const float* embb  = (const float*)d_in[6];
    const float* l1w   = (const float*)d_in[7];
    const float* l1b   = (const float*)d_in[8];
    const float* l2w   = (const float*)d_in[9];
    const float* l3w   = (const float*)d_in[10];
    const float* l3b   = (const float*)d_in[11];
    const float* f1w   = (const float*)d_in[12];
    const float* f1b   = (const float*)d_in[13];
    const float* f2w   = (const float*)d_in[14];
    const float* f2b   = (const float*)d_in[15];
    float* out = (float*)d_out;

    const int smem_mega = (128 * 68 + 64 * 200) * 4;  // 86016 B
    cudaFuncSetAttribute(k_mega, cudaFuncAttributeMaxDynamicSharedMemorySize, smem_mega);

    int sms = 148;
    cudaDeviceGetAttribute(&sms, cudaDevAttrMultiProcessorCount, 0);
    int nb = sms * 2;  // all resident: __launch_bounds__(256,2), 2*86016B <= smem/SM

    const int* src = ei;
    const int* dst = ei + NE;

    k_init<<<(NN * 32 + 255) / 256, 256>>>(x, embw, embb);
    k_edge<<<(NE / 4 + 255) / 256, 256>>>(src, dst, eatt);
    k_scan<<<(NN + 1023) / 1024, 256>>>();
    k_fill<<<(NE / 4 + 255) / 256, 256>>>(src, dst, eattr, eatt);
    k_mega<<<nb, 256, smem_mega>>>(l1w, l1b, l2w, l3w, l3b, batch,
                                   f1w, f1b, f2w, f2b, out, nb);
}

// round 8
// speedup vs baseline: 1.2109x; 1.2109x over previous
#include <cuda_runtime.h>
#include <cuda_fp16.h>
#include <cstdint>

#define NN 100000
#define NE 1000000
#define NGR 512

// ---------------- scratch ----------------
__device__ float g_Win[NN];       // sum of incoming edge weights (atomic, fill)
__device__ float g_atts[NN];      // src-side attention sum (atomic, edge)
__device__ float g_attd[NN];      // dst-side attention sum (atomic, fill)
__device__ int   g_degs[NN];      // src-side degree (atomic, edge)
__device__ int   g_cnt[NN];       // in-degree (CSR row counts)
__device__ int   g_rs[NN];        // CSR row start
__device__ int   g_cur[NN];       // CSR fill cursor
__device__ int   g_bsum[128];     // chained-scan flags
__device__ int   g_tick;
__device__ float2 g_ce[NE];       // CSR: {src_as_bits, w}
__device__ __half g_hh[NN * 64];
__device__ __half g_Ah[NN * 64];
__device__ __half g_Dh[NN * 64];

__device__ __forceinline__ uint32_t f2tf32(float f) {
    uint32_t o;
    asm("cvt.rna.tf32.f32 %0, %1;" : "=r"(o) : "f"(f));
    return o;
}

// ---------------- init: zero scratch + node embedding (h fp16) ----------------
__global__ void k_init(const float* __restrict__ x, const float* __restrict__ w,
                       const float* __restrict__ b) {
    int gid = blockIdx.x * 256 + threadIdx.x;
    if (gid < NN) {
        g_atts[gid] = 0.f; g_attd[gid] = 0.f; g_Win[gid] = 0.f;
        g_degs[gid] = 0; g_cnt[gid] = 0;
    }
    if (gid < 128) g_bsum[gid] = 0;
    if (gid == 0) g_tick = 0;
    if (gid < NN * 32) {
        int i = gid >> 5, c = (gid & 31) * 2;
        float x0 = x[i * 4], x1 = x[i * 4 + 1], x2 = x[i * 4 + 2], x3 = x[i * 4 + 3];
        float h0 = b[c]     + x0 * w[c]     + x1 * w[64 + c]     + x2 * w[128 + c]     + x3 * w[192 + c];
        float h1 = b[c + 1] + x0 * w[c + 1] + x1 * w[64 + c + 1] + x2 * w[128 + c + 1] + x3 * w[192 + c + 1];
        *(__half2*)&g_hh[i * 64 + c] = __floats2half2_rn(h0, h1);
    }
}

// ---------------- edge pass: dst histogram + src-side atomics ----------------
__global__ void k_edge(const int* __restrict__ src, const int* __restrict__ dst,
                       const float* __restrict__ atten) {
    int e4 = blockIdx.x * 256 + threadIdx.x;
    if (e4 * 4 >= NE) return;
    int4 s = *(const int4*)&src[e4 * 4];
    int4 d = *(const int4*)&dst[e4 * 4];
    float4 at = *(const float4*)&atten[e4 * 4];
    atomicAdd(&g_cnt[d.x], 1); atomicAdd(&g_cnt[d.y], 1);
    atomicAdd(&g_cnt[d.z], 1); atomicAdd(&g_cnt[d.w], 1);
    atomicAdd(&g_atts[s.x], at.x); atomicAdd(&g_atts[s.y], at.y);
    atomicAdd(&g_atts[s.z], at.z); atomicAdd(&g_atts[s.w], at.w);
    atomicAdd(&g_degs[s.x], 1); atomicAdd(&g_degs[s.y], 1);
    atomicAdd(&g_degs[s.z], 1); atomicAdd(&g_degs[s.w], 1);
}

// ---------------- single-pass chained exclusive scan ----------------
__global__ void k_scan() {
    __shared__ int sm_t, sm_prev, wsum[8];
    int tid = threadIdx.x;
    if (tid == 0) sm_t = atomicAdd(&g_tick, 1);
    __syncthreads();
    int t = sm_t;
    int base = t * 1024 + tid * 4;
    int v0 = 0, v1 = 0, v2 = 0, v3 = 0;
    if (base + 3 < NN) {
        int4 q = *(const int4*)&g_cnt[base];
        v0 = q.x; v1 = q.y; v2 = q.z; v3 = q.w;
    } else {
        if (base < NN)     v0 = g_cnt[base];
        if (base + 1 < NN) v1 = g_cnt[base + 1];
        if (base + 2 < NN) v2 = g_cnt[base + 2];
        if (base + 3 < NN) v3 = g_cnt[base + 3];
    }
    int sloc = v0 + v1 + v2 + v3;
    int x = sloc;
#pragma unroll
    for (int o = 1; o < 32; o <<= 1) {
        int y = __shfl_up_sync(0xffffffffu, x, o);
        if ((tid & 31) >= o) x += y;
    }
    if ((tid & 31) == 31) wsum[tid >> 5] = x;
    __syncthreads();
    if (tid < 8) {
        int y = wsum[tid];
#pragma unroll
        for (int o = 1; o < 8; o <<= 1) {
            int z = __shfl_up_sync(0xffu, y, o);
            if (tid >= o) y += z;
        }
        wsum[tid] = y;
    }
    __syncthreads();
    int woff = (tid >= 32) ? wsum[(tid >> 5) - 1] : 0;
    int excl = x - sloc + woff;
    int total = wsum[7];
    if (tid == 0) {
        int prev = 0;
        if (t > 0) {
            int v;
            while ((v = atomicAdd(&g_bsum[t - 1], 0)) == 0) {}
            prev = v - 1;
        }
        atomicExch(&g_bsum[t], prev + total + 1);
        sm_prev = prev;
    }
    __syncthreads();
    int off = sm_prev + excl;
    if (base < NN)     { g_rs[base]     = off;                g_cur[base]     = off; }
    if (base + 1 < NN) { g_rs[base + 1] = off + v0;           g_cur[base + 1] = off + v0; }
    if (base + 2 < NN) { g_rs[base + 2] = off + v0 + v1;      g_cur[base + 2] = off + v0 + v1; }
    if (base + 3 < NN) { g_rs[base + 3] = off + v0 + v1 + v2; g_cur[base + 3] = off + v0 + v1 + v2; }
}

// ---------------- CSR fill + dst-side atomics (4 edges/thread) ----------------
__global__ void k_fill(const int* __restrict__ src, const int* __restrict__ dst,
                       const float* __restrict__ attr, const float* __restrict__ atten) {
    int e4 = blockIdx.x * 256 + threadIdx.x;
    if (e4 * 4 >= NE) return;
    int4 s = *(const int4*)&src[e4 * 4];
    int4 d = *(const int4*)&dst[e4 * 4];
    float4 ar = *(const float4*)&attr[e4 * 4];
    float4 at = *(const float4*)&atten[e4 * 4];
    int p0 = atomicAdd(&g_cur[d.x], 1);
    int p1 = atomicAdd(&g_cur[d.y], 1);
    int p2 = atomicAdd(&g_cur[d.z], 1);
    int p3 = atomicAdd(&g_cur[d.w], 1);
    float w0 = ar.x * at.x, w1 = ar.y * at.y, w2 = ar.z * at.z, w3 = ar.w * at.w;
    g_ce[p0] = make_float2(__int_as_float(s.x), w0);
    g_ce[p1] = make_float2(__int_as_float(s.y), w1);
    g_ce[p2] = make_float2(__int_as_float(s.z), w2);
    g_ce[p3] = make_float2(__int_as_float(s.w), w3);
    atomicAdd(&g_Win[d.x], w0); atomicAdd(&g_Win[d.y], w1);
    atomicAdd(&g_Win[d.z], w2); atomicAdd(&g_Win[d.w], w3);
    atomicAdd(&g_attd[d.x], at.x); atomicAdd(&g_attd[d.y], at.y);
    atomicAdd(&g_attd[d.z], at.z); atomicAdd(&g_attd[d.w], at.w);
}

// ---------------- layer GEMM via mma.sync tf32 (h fp16 in, A/D fp16 out) -----
__global__ void __launch_bounds__(256, 2) k_gemm(const float* __restrict__ W1,
                                                 const float* __restrict__ W2,
                                                 const float* __restrict__ W3,
                                                 const float* __restrict__ b1,
                                                 const float* __restrict__ b3) {
    extern __shared__ float sm[];
    float* sh_h = sm;              // [128][68] tf32 words
    float* sh_w = sm + 128 * 68;   // [64][200]
    int tid = threadIdx.x;
    int nbase = blockIdx.x * 128;

    for (int i = tid; i < 1024; i += 256) {
        int node = i >> 3, k8 = (i & 7) << 3;
        int gn = nbase + node;
        uint4 v = make_uint4(0u, 0u, 0u, 0u);
        if (gn < NN) v = *(const uint4*)&g_hh[gn * 64 + k8];
        __half2* hv = (__half2*)&v;
        uint32_t* p = (uint32_t*)&sh_h[node * 68 + k8];
#pragma unroll
        for (int j = 0; j < 4; j++) {
            float2 f = __half22float2(hv[j]);
            p[2 * j] = f2tf32(f.x); p[2 * j + 1] = f2tf32(f.y);
        }
    }
    for (int i = tid; i < 3072; i += 256) {
        int row = i / 48;
        int q = i % 48;
        int m = q >> 4, c4 = (q & 15) << 2;
        const float* Wm = (m == 0) ? W1 : ((m == 1) ? W2 : W3);
        float4 v = *(const float4*)&Wm[row * 64 + c4];
        uint32_t* p = (uint32_t*)&sh_w[row * 200 + m * 64 + c4];
        p[0] = f2tf32(v.x); p[1] = f2tf32(v.y); p[2] = f2tf32(v.z); p[3] = f2tf32(v.w);
    }
    __syncthreads();

    int w = tid >> 5, lane = tid & 31;
    int rowG = w & 3, colH = w >> 2;
    int gid = lane >> 2, tid4 = lane & 3;

    float acc[24][4];
#pragma unroll
    for (int t = 0; t < 24; t++) {
        acc[t][0] = 0.f; acc[t][1] = 0.f; acc[t][2] = 0.f; acc[t][3] = 0.f;
    }

    const uint32_t* hp = (const uint32_t*)(sh_h + rowG * 32 * 68);
    const uint32_t* wp = (const uint32_t*)sh_w;

#pragma unroll
    for (int kt = 0; kt < 8; kt++) {
        int k0 = kt * 8;
        uint32_t a[2][4];
#pragma unroll
        for (int rt = 0; rt < 2; rt++) {
            const uint32_t* hq = hp + rt * 16 * 68;
            a[rt][0] = hq[gid * 68 + k0 + tid4];
            a[rt][1] = hq[(gid + 8) * 68 + k0 + tid4];
            a[rt][2] = hq[gid * 68 + k0 + tid4 + 4];
            a[rt][3] = hq[(gid + 8) * 68 + k0 + tid4 + 4];
        }
#pragma unroll
        for (int m = 0; m < 3; m++) {
#pragma unroll
            for (int tt = 0; tt < 4; tt++) {
                int nb = m * 64 + colH * 32 + tt * 8;
                uint32_t bb0 = wp[(k0 + tid4) * 200 + nb + gid];
                uint32_t bb1 = wp[(k0 + tid4 + 4) * 200 + nb + gid];
#pragma unroll
                for (int rt = 0; rt < 2; rt++) {
                    float* c = acc[rt * 12 + m * 4 + tt];
                    asm volatile(
                        "mma.sync.aligned.m16n8k8.row.col.f32.tf32.tf32.f32 "
                        "{%0,%1,%2,%3}, {%4,%5,%6,%7}, {%8,%9}, {%0,%1,%2,%3};"
                        : "+f"(c[0]), "+f"(c[1]), "+f"(c[2]), "+f"(c[3])
                        : "r"(a[rt][0]), "r"(a[rt][1]), "r"(a[rt][2]), "r"(a[rt][3]),
                          "r"(bb0), "r"(bb1));
                }
            }
        }
    }

#pragma unroll
    for (int rt = 0; rt < 2; rt++) {
        int r1 = nbase + rowG * 32 + rt * 16 + gid;
        int r2 = r1 + 8;
        float win1 = (r1 < NN) ? g_Win[r1] : 0.f;
        float win2 = (r2 < NN) ? g_Win[r2] : 0.f;
#pragma unroll
        for (int tt = 0; tt < 4; tt++) {
            int c = colH * 32 + tt * 8 + tid4 * 2;
            float2 b1v = *(const float2*)&b1[c];
            float2 b3v = *(const float2*)&b3[c];
            float* aW1 = acc[rt * 12 + tt];
            float* aW2 = acc[rt * 12 + 4 + tt];
            float* aW3 = acc[rt * 12 + 8 + tt];
            if (r1 < NN) {
                *(__half2*)&g_Ah[r1 * 64 + c] =
                    __floats2half2_rn(aW1[0] + b1v.x, aW1[1] + b1v.y);
                *(__half2*)&g_Dh[r1 * 64 + c] =
                    __floats2half2_rn(aW3[0] + b3v.x - win1 * aW2[0],
                                      aW3[1] + b3v.y - win1 * aW2[1]);
            }
            if (r2 < NN) {
                *(__half2*)&g_Ah[r2 * 64 + c] =
                    __floats2half2_rn(aW1[2] + b1v.x, aW1[3] + b1v.y);
                *(__half2*)&g_Dh[r2 * 64 + c] =
                    __floats2half2_rn(aW3[2] + b3v.x - win2 * aW2[2],
                                      aW3[3] + b3v.y - win2 * aW2[3]);
            }
        }
    }
}

// ---------------- gather: h = relu( sum_e w*A[src] + D ), warp per node ------
__global__ void k_gather() {
    int gt = blockIdx.x * 256 + threadIdx.x;
    int node = gt >> 5, lane = gt & 31;
    if (node >= NN) return;
    int s = g_rs[node];
    int e = s + g_cnt[node];
    int loff = lane * 2;
    float ax0 = 0.f, ay0 = 0.f, ax1 = 0.f, ay1 = 0.f;
    for (int base = s; base < e; base += 32) {
        int idx = base + lane;
        float2 ce = make_float2(0.f, 0.f);
        if (idx < e) ce = g_ce[idx];
        int sn = __float_as_int(ce.x);
        float wv = ce.y;
        int m = min(32, e - base);
        int mr = (m + 3) & ~3;
        for (int j = 0; j < mr; j += 4) {
            int s0 = __shfl_sync(0xffffffffu, sn, j);
            int s1 = __shfl_sync(0xffffffffu, sn, j + 1);
            int s2 = __shfl_sync(0xffffffffu, sn, j + 2);
            int s3 = __shfl_sync(0xffffffffu, sn, j + 3);
            float w0 = __shfl_sync(0xffffffffu, wv, j);
            float w1 = __shfl_sync(0xffffffffu, wv, j + 1);
            float w2 = __shfl_sync(0xffffffffu, wv, j + 2);
            float w3 = __shfl_sync(0xffffffffu, wv, j + 3);
            __half2 h0 = __ldg((const __half2*)&g_Ah[s0 * 64 + loff]);
            __half2 h1 = __ldg((const __half2*)&g_Ah[s1 * 64 + loff]);
            __half2 h2 = __ldg((const __half2*)&g_Ah[s2 * 64 + loff]);
            __half2 h3 = __ldg((const __half2*)&g_Ah[s3 * 64 + loff]);
            float2 v0 = __half22float2(h0);
            float2 v1 = __half22float2(h1);
            float2 v2 = __half22float2(h2);
            float2 v3 = __half22float2(h3);
            ax0 = fmaf(w0, v0.x, ax0); ay0 = fmaf(w0, v0.y, ay0);
            ax1 = fmaf(w1, v1.x, ax1); ay1 = fmaf(w1, v1.y, ay1);
            ax0 = fmaf(w2, v2.x, ax0); ay0 = fmaf(w2, v2.y, ay0);
            ax1 = fmaf(w3, v3.x, ax1); ay1 = fmaf(w3, v3.y, ay1);
        }
    }
    float2 dv = __half22float2(*(const __half2*)&g_Dh[node * 64 + loff]);
    *(__half2*)&g_hh[node * 64 + loff] =
        __floats2half2_rn(fmaxf(ax0 + ax1 + dv.x, 0.f), fmaxf(ay0 + ay1 + dv.y, 0.f));
}

// ---------------- fused pooling + MLP (one block per graph, 128 threads) -----
__global__ void k_poolmlp(const int* __restrict__ batch,
                          const float* __restrict__ f1w, const float* __restrict__ f1b,
                          const float* __restrict__ f2w, const float* __restrict__ f2b,
                          float* __restrict__ out) {
    int g = blockIdx.x, tid = threadIdx.x;  // 128
    __shared__ int se[2];
    __shared__ float sacc[128], satt[128];
    __shared__ float sx[64], shh[128];
    if (tid < 2) {
        int key = g + tid;
        int lo = 0, hi = NN;
        while (lo < hi) {
            int mid = (lo + hi) >> 1;
            if (batch[mid] < key) lo = mid + 1; else hi = mid;
        }
        se[tid] = lo;
    }
    __syncthreads();
    int s = se[0], e = se[1];
    int c = tid & 63, part = tid >> 6;
    float acc = 0.f, att = 0.f;
    for (int i = s + part; i < e; i += 2) {
        int dg = g_degs[i] + g_cnt[i];
        float na = (g_atts[i] + g_attd[i]) / ((dg == 0) ? 1.f : (float)dg);
        acc = fmaf(__half2float(g_hh[i * 64 + c]), na, acc);
        att += na;
    }
    sacc[tid] = acc; satt[tid] = att;
    __syncthreads();
    if (tid < 64) {
        float a = sacc[tid] + sacc[tid + 64];
        float at = satt[0] + satt[64];
        float cnt = (float)(e - s);
        float gat = (at == 0.f) ? 1.f : at;
        float scale = cnt / (gat * fmaxf(cnt, 1.f));
        sx[tid] = a * scale;
    }
    __syncthreads();
    float a = f1b[tid];
#pragma unroll 8
    for (int k = 0; k < 64; k++) a = fmaf(sx[k], f1w[k * 128 + tid], a);
    shh[tid] = fmaxf(a, 0.f);
    __syncthreads();
    if (tid < 3) {
        float o = f2b[tid];
        for (int j = 0; j < 128; j++) o = fmaf(shh[j], f2w[j * 3 + tid], o);
        out[g * 3 + tid] = o;
    }
}

// ---------------- launch ----------------
extern "C" void kernel_launch(void* const* d_in, const int* in_sizes, int n_in,
                              void* d_out, int out_size) {
    const float* x     = (const float*)d_in[0];
    const int*   ei    = (const int*)d_in[1];
    const int*   batch = (const int*)d_in[2];
    const float* eattr = (const float*)d_in[3];
    const float* eatt  = (const float*)d_in[4];
    const float* embw  = (const float*)d_in[5];
    const float* embb  = (const float*)d_in[6];
    const float* l1w   = (const float*)d_in[7];
    const float* l1b   = (const float*)d_in[8];
    const float* l2w   = (const float*)d_in[9];
    const float* l3w   = (const float*)d_in[10];
    const float* l3b   = (const float*)d_in[11];
    const float* f1w   = (const float*)d_in[12];
    const float* f1b   = (const float*)d_in[13];
    const float* f2w   = (const float*)d_in[14];
    const float* f2b   = (const float*)d_in[15];
    float* out = (float*)d_out;

    const int smem_gemm = (128 * 68 + 64 * 200) * 4;  // 86016 B
    cudaFuncSetAttribute(k_gemm, cudaFuncAttributeMaxDynamicSharedMemorySize, smem_gemm);

    const int* src = ei;
    const int* dst = ei + NE;

    k_init<<<(NN * 32 + 255) / 256, 256>>>(x, embw, embb);
    k_edge<<<(NE / 4 + 255) / 256, 256>>>(src, dst, eatt);
    k_scan<<<(NN + 1023) / 1024, 256>>>();
    k_fill<<<(NE / 4 + 255) / 256, 256>>>(src, dst, eattr, eatt);

    for (int l = 0; l < 3; l++) {
        k_gemm<<<(NN + 127) / 128, 256, smem_gemm>>>(
            l1w + l * 4096, l2w + l * 4096, l3w + l * 4096,
            l1b + l * 64, l3b + l * 64);
        k_gather<<<(NN * 32 + 255) / 256, 256>>>();
    }

    k_poolmlp<<<NGR, 128>>>(batch, f1w, f1b, f2w, f2b, out);
}

// round 9
// speedup vs baseline: 1.2631x; 1.0431x over previous
#include <cuda_runtime.h>
#include <cuda_fp16.h>
#include <cstdint>

#define NN 100000
#define NE 1000000
#define NGR 512

// ---------------- scratch ----------------
__device__ float g_Win[NN];       // sum of incoming edge weights (row sums)
__device__ float g_atts[NN];      // src-side attention sum (atomic)
__device__ int   g_degs[NN];      // src-side degree (atomic)
__device__ float g_natt[NN];      // final node attention
__device__ int   g_cnt[NN];       // in-degree (CSR row counts)
__device__ int   g_rs[NN];        // CSR row start
__device__ int   g_cur[NN];       // CSR fill cursor
__device__ int   g_bsum[128];     // chained-scan flags
__device__ int   g_tick;
__device__ float2 g_ce[NE];       // CSR: {src_as_bits, w}
__device__ float g_catt[NE];      // CSR: atten per slot
__device__ __half g_hh[NN * 64];  // h in fp16
__device__ __half g_Ah[NN * 64];  // A in fp16
__device__ __half g_Dh[NN * 64];  // D in fp16

__device__ __forceinline__ uint32_t f2tf32(float f) {
    uint32_t o;
    asm("cvt.rna.tf32.f32 %0, %1;" : "=r"(o) : "f"(f));
    return o;
}

// ---------------- init: zero scratch + node embedding (h fp16) ----------------
__global__ void k_init(const float* __restrict__ x, const float* __restrict__ w,
                       const float* __restrict__ b) {
    int gid = blockIdx.x * 256 + threadIdx.x;
    if (gid < NN) { g_atts[gid] = 0.f; g_degs[gid] = 0; g_cnt[gid] = 0; }
    if (gid < 128) g_bsum[gid] = 0;
    if (gid == 0) g_tick = 0;
    if (gid < NN * 32) {
        int i = gid >> 5, c = (gid & 31) * 2;
        float x0 = x[i * 4], x1 = x[i * 4 + 1], x2 = x[i * 4 + 2], x3 = x[i * 4 + 3];
        float h0 = b[c]     + x0 * w[c]     + x1 * w[64 + c]     + x2 * w[128 + c]     + x3 * w[192 + c];
        float h1 = b[c + 1] + x0 * w[c + 1] + x1 * w[64 + c + 1] + x2 * w[128 + c + 1] + x3 * w[192 + c + 1];
        *(__half2*)&g_hh[i * 64 + c] = __floats2half2_rn(h0, h1);
    }
}

// ---------------- edge pass: dst in-degree histogram only ----------------
__global__ void k_edge(const int* __restrict__ dst) {
    int e4 = blockIdx.x * 256 + threadIdx.x;
    if (e4 * 4 >= NE) return;
    int4 d = *(const int4*)&dst[e4 * 4];
    atomicAdd(&g_cnt[d.x], 1); atomicAdd(&g_cnt[d.y], 1);
    atomicAdd(&g_cnt[d.z], 1); atomicAdd(&g_cnt[d.w], 1);
}

// ---------------- single-pass chained exclusive scan: g_cnt -> g_rs, g_cur ----
__global__ void k_scan() {
    __shared__ int sm_t, sm_prev, wsum[8];
    int tid = threadIdx.x;
    if (tid == 0) sm_t = atomicAdd(&g_tick, 1);
    __syncthreads();
    int t = sm_t;
    int base = t * 1024 + tid * 4;
    int v0 = 0, v1 = 0, v2 = 0, v3 = 0;
    if (base + 3 < NN) {
        int4 q = *(const int4*)&g_cnt[base];
        v0 = q.x; v1 = q.y; v2 = q.z; v3 = q.w;
    } else {
        if (base < NN)     v0 = g_cnt[base];
        if (base + 1 < NN) v1 = g_cnt[base + 1];
        if (base + 2 < NN) v2 = g_cnt[base + 2];
        if (base + 3 < NN) v3 = g_cnt[base + 3];
    }
    int sloc = v0 + v1 + v2 + v3;
    int x = sloc;
#pragma unroll
    for (int o = 1; o < 32; o <<= 1) {
        int y = __shfl_up_sync(0xffffffffu, x, o);
        if ((tid & 31) >= o) x += y;
    }
    if ((tid & 31) == 31) wsum[tid >> 5] = x;
    __syncthreads();
    if (tid < 8) {
        int y = wsum[tid];
#pragma unroll
        for (int o = 1; o < 8; o <<= 1) {
            int z = __shfl_up_sync(0xffu, y, o);
            if (tid >= o) y += z;
        }
        wsum[tid] = y;
    }
    __syncthreads();
    int woff = (tid >= 32) ? wsum[(tid >> 5) - 1] : 0;
    int excl = x - sloc + woff;
    int total = wsum[7];
    if (tid == 0) {
        int prev = 0;
        if (t > 0) {
            int v;
            while ((v = atomicAdd(&g_bsum[t - 1], 0)) == 0) {}
            prev = v - 1;
        }
        atomicExch(&g_bsum[t], prev + total + 1);
        sm_prev = prev;
    }
    __syncthreads();
    int off = sm_prev + excl;
    if (base < NN)     { g_rs[base]     = off;                g_cur[base]     = off; }
    if (base + 1 < NN) { g_rs[base + 1] = off + v0;           g_cur[base + 1] = off + v0; }
    if (base + 2 < NN) { g_rs[base + 2] = off + v0 + v1;      g_cur[base + 2] = off + v0 + v1; }
    if (base + 3 < NN) { g_rs[base + 3] = off + v0 + v1 + v2; g_cur[base + 3] = off + v0 + v1 + v2; }
}

// ---------------- CSR fill + src-side atomics (4 edges/thread) ----------------
__global__ void k_fill(const int* __restrict__ src, const int* __restrict__ dst,
                       const float* __restrict__ attr, const float* __restrict__ atten) {
    int e4 = blockIdx.x * 256 + threadIdx.x;
    if (e4 * 4 >= NE) return;
    int4 s = *(const int4*)&src[e4 * 4];
    int4 d = *(const int4*)&dst[e4 * 4];
    float4 ar = *(const float4*)&attr[e4 * 4];
    float4 at = *(const float4*)&atten[e4 * 4];
    int p0 = atomicAdd(&g_cur[d.x], 1);
    int p1 = atomicAdd(&g_cur[d.y], 1);
    int p2 = atomicAdd(&g_cur[d.z], 1);
    int p3 = atomicAdd(&g_cur[d.w], 1);
    g_ce[p0] = make_float2(__int_as_float(s.x), ar.x * at.x);
    g_ce[p1] = make_float2(__int_as_float(s.y), ar.y * at.y);
    g_ce[p2] = make_float2(__int_as_float(s.z), ar.z * at.z);
    g_ce[p3] = make_float2(__int_as_float(s.w), ar.w * at.w);
    g_catt[p0] = at.x;
    g_catt[p1] = at.y;
    g_catt[p2] = at.z;
    g_catt[p3] = at.w;
    atomicAdd(&g_atts[s.x], at.x); atomicAdd(&g_atts[s.y], at.y);
    atomicAdd(&g_atts[s.z], at.z); atomicAdd(&g_atts[s.w], at.w);
    atomicAdd(&g_degs[s.x], 1);    atomicAdd(&g_degs[s.y], 1);
    atomicAdd(&g_degs[s.z], 1);    atomicAdd(&g_degs[s.w], 1);
}

// ---------------- row stats: Win, natt (warp per node, sequential reads) -----
__global__ void k_rowstats() {
    int gt = blockIdx.x * 256 + threadIdx.x;
    int node = gt >> 5, lane = gt & 31;
    if (node >= NN) return;
    int s = g_rs[node];
    int len = g_cnt[node];
    float wsum = 0.f, asum = 0.f;
    for (int i = lane; i < len; i += 32) {
        wsum += g_ce[s + i].y;
        asum += g_catt[s + i];
    }
#pragma unroll
    for (int o = 16; o > 0; o >>= 1) {
        wsum += __shfl_down_sync(0xffffffffu, wsum, o);
        asum += __shfl_down_sync(0xffffffffu, asum, o);
    }
    if (lane == 0) {
        g_Win[node] = wsum;
        float att_tot = asum + g_atts[node];
        float deg = (float)(len + g_degs[node]);
        g_natt[node] = att_tot / ((deg == 0.f) ? 1.f : deg);
    }
}

// ---------------- layer GEMM via mma.sync tf32 (h fp16 in, A/D fp16 out) -----
__global__ void __launch_bounds__(256, 2) k_gemm(const float* __restrict__ W1,
                                                 const float* __restrict__ W2,
                                                 const float* __restrict__ W3,
                                                 const float* __restrict__ b1,
                                                 const float* __restrict__ b3) {
    extern __shared__ float sm[];
    float* sh_h = sm;              // [128][68] tf32 words
    float* sh_w = sm + 128 * 68;   // [64][200]
    int tid = threadIdx.x;
    int nbase = blockIdx.x * 128;

    for (int i = tid; i < 1024; i += 256) {
        int node = i >> 3, k8 = (i & 7) << 3;
        int gn = nbase + node;
        uint4 v = make_uint4(0u, 0u, 0u, 0u);
        if (gn < NN) v = *(const uint4*)&g_hh[gn * 64 + k8];
        __half2* hv = (__half2*)&v;
        uint32_t* p = (uint32_t*)&sh_h[node * 68 + k8];
#pragma unroll
        for (int j = 0; j < 4; j++) {
            float2 f = __half22float2(hv[j]);
            p[2 * j] = f2tf32(f.x); p[2 * j + 1] = f2tf32(f.y);
        }
    }
    for (int i = tid; i < 3072; i += 256) {
        int row = i / 48;
        int q = i % 48;
        int m = q >> 4, c4 = (q & 15) << 2;
        const float* Wm = (m == 0) ? W1 : ((m == 1) ? W2 : W3);
        float4 v = *(const float4*)&Wm[row * 64 + c4];
        uint32_t* p = (uint32_t*)&sh_w[row * 200 + m * 64 + c4];
        p[0] = f2tf32(v.x); p[1] = f2tf32(v.y); p[2] = f2tf32(v.z); p[3] = f2tf32(v.w);
    }
    __syncthreads();

    int w = tid >> 5, lane = tid & 31;
    int rowG = w & 3, colH = w >> 2;
    int gid = lane >> 2, tid4 = lane & 3;

    float acc[24][4];
#pragma unroll
    for (int t = 0; t < 24; t++) {
        acc[t][0] = 0.f; acc[t][1] = 0.f; acc[t][2] = 0.f; acc[t][3] = 0.f;
    }

    const uint32_t* hp = (const uint32_t*)(sh_h + rowG * 32 * 68);
    const uint32_t* wp = (const uint32_t*)sh_w;

#pragma unroll
    for (int kt = 0; kt < 8; kt++) {
        int k0 = kt * 8;
        uint32_t a[2][4];
#pragma unroll
        for (int rt = 0; rt < 2; rt++) {
            const uint32_t* hq = hp + rt * 16 * 68;
            a[rt][0] = hq[gid * 68 + k0 + tid4];
            a[rt][1] = hq[(gid + 8) * 68 + k0 + tid4];
            a[rt][2] = hq[gid * 68 + k0 + tid4 + 4];
            a[rt][3] = hq[(gid + 8) * 68 + k0 + tid4 + 4];
        }
#pragma unroll
        for (int m = 0; m < 3; m++) {
#pragma unroll
            for (int tt = 0; tt < 4; tt++) {
                int nb = m * 64 + colH * 32 + tt * 8;
                uint32_t bb0 = wp[(k0 + tid4) * 200 + nb + gid];
                uint32_t bb1 = wp[(k0 + tid4 + 4) * 200 + nb + gid];
#pragma unroll
                for (int rt = 0; rt < 2; rt++) {
                    float* c = acc[rt * 12 + m * 4 + tt];
                    asm volatile(
                        "mma.sync.aligned.m16n8k8.row.col.f32.tf32.tf32.f32 "
                        "{%0,%1,%2,%3}, {%4,%5,%6,%7}, {%8,%9}, {%0,%1,%2,%3};"
                        : "+f"(c[0]), "+f"(c[1]), "+f"(c[2]), "+f"(c[3])
                        : "r"(a[rt][0]), "r"(a[rt][1]), "r"(a[rt][2]), "r"(a[rt][3]),
                          "r"(bb0), "r"(bb1));
                }
            }
        }
    }

#pragma unroll
    for (int rt = 0; rt < 2; rt++) {
        int r1 = nbase + rowG * 32 + rt * 16 + gid;
        int r2 = r1 + 8;
        float win1 = (r1 < NN) ? g_Win[r1] : 0.f;
        float win2 = (r2 < NN) ? g_Win[r2] : 0.f;
#pragma unroll
        for (int tt = 0; tt < 4; tt++) {
            int c = colH * 32 + tt * 8 + tid4 * 2;
            float2 b1v = *(const float2*)&b1[c];
            float2 b3v = *(const float2*)&b3[c];
            float* aW1 = acc[rt * 12 + tt];
            float* aW2 = acc[rt * 12 + 4 + tt];
            float* aW3 = acc[rt * 12 + 8 + tt];
            if (r1 < NN) {
                *(__half2*)&g_Ah[r1 * 64 + c] =
                    __floats2half2_rn(aW1[0] + b1v.x, aW1[1] + b1v.y);
                *(__half2*)&g_Dh[r1 * 64 + c] =
                    __floats2half2_rn(aW3[0] + b3v.x - win1 * aW2[0],
                                      aW3[1] + b3v.y - win1 * aW2[1]);
            }
            if (r2 < NN) {
                *(__half2*)&g_Ah[r2 * 64 + c] =
                    __floats2half2_rn(aW1[2] + b1v.x, aW1[3] + b1v.y);
                *(__half2*)&g_Dh[r2 * 64 + c] =
                    __floats2half2_rn(aW3[2] + b3v.x - win2 * aW2[2],
                                      aW3[3] + b3v.y - win2 * aW2[3]);
            }
        }
    }
}

// ---------------- gather: h = relu( sum_e w*A[src] + D ), warp per node ------
__global__ void k_gather() {
    int gt = blockIdx.x * 256 + threadIdx.x;
    int node = gt >> 5, lane = gt & 31;
    if (node >= NN) return;
    int s = g_rs[node];
    int e = s + g_cnt[node];
    int loff = lane * 2;
    float ax0 = 0.f, ay0 = 0.f, ax1 = 0.f, ay1 = 0.f;
    for (int base = s; base < e; base += 32) {
        int idx = base + lane;
        float2 ce = make_float2(0.f, 0.f);
        if (idx < e) ce = g_ce[idx];
        int sn = __float_as_int(ce.x);
        float wv = ce.y;
        int m = min(32, e - base);
        int mr = (m + 3) & ~3;
        for (int j = 0; j < mr; j += 4) {
            int s0 = __shfl_sync(0xffffffffu, sn, j);
            int s1 = __shfl_sync(0xffffffffu, sn, j + 1);
            int s2 = __shfl_sync(0xffffffffu, sn, j + 2);
            int s3 = __shfl_sync(0xffffffffu, sn, j + 3);
            float w0 = __shfl_sync(0xffffffffu, wv, j);
            float w1 = __shfl_sync(0xffffffffu, wv, j + 1);
            float w2 = __shfl_sync(0xffffffffu, wv, j + 2);
            float w3 = __shfl_sync(0xffffffffu, wv, j + 3);
            __half2 h0 = __ldg((const __half2*)&g_Ah[s0 * 64 + loff]);
            __half2 h1 = __ldg((const __half2*)&g_Ah[s1 * 64 + loff]);
            __half2 h2 = __ldg((const __half2*)&g_Ah[s2 * 64 + loff]);
            __half2 h3 = __ldg((const __half2*)&g_Ah[s3 * 64 + loff]);
            float2 v0 = __half22float2(h0);
            float2 v1 = __half22float2(h1);
            float2 v2 = __half22float2(h2);
            float2 v3 = __half22float2(h3);
            ax0 = fmaf(w0, v0.x, ax0); ay0 = fmaf(w0, v0.y, ay0);
            ax1 = fmaf(w1, v1.x, ax1); ay1 = fmaf(w1, v1.y, ay1);
            ax0 = fmaf(w2, v2.x, ax0); ay0 = fmaf(w2, v2.y, ay0);
            ax1 = fmaf(w3, v3.x, ax1); ay1 = fmaf(w3, v3.y, ay1);
        }
    }
    float2 dv = __half22float2(*(const __half2*)&g_Dh[node * 64 + loff]);
    *(__half2*)&g_hh[node * 64 + loff] =
        __floats2half2_rn(fmaxf(ax0 + ax1 + dv.x, 0.f), fmaxf(ay0 + ay1 + dv.y, 0.f));
}

// ---------------- fused pooling + MLP (one block per graph, 128 threads) -----
__global__ void k_poolmlp(const int* __restrict__ batch,
                          const float* __restrict__ f1w, const float* __restrict__ f1b,
                          const float* __restrict__ f2w, const float* __restrict__ f2b,
                          float* __restrict__ out) {
    int g = blockIdx.x, tid = threadIdx.x;  // 128
    __shared__ int se[2];
    __shared__ float sacc[128], satt[128];
    __shared__ float sx[64], shh[128];
    if (tid < 2) {
        int key = g + tid;
        int lo = 0, hi = NN;
        while (lo < hi) {
            int mid = (lo + hi) >> 1;
            if (batch[mid] < key) lo = mid + 1; else hi = mid;
        }
        se[tid] = lo;
    }
    __syncthreads();
    int s = se[0], e = se[1];
    int c = tid & 63, part = tid >> 6;
    float acc = 0.f, att = 0.f;
    for (int i = s + part; i < e; i += 2) {
        float na = g_natt[i];
        acc = fmaf(__half2float(g_hh[i * 64 + c]), na, acc);
        att += na;
    }
    sacc[tid] = acc; satt[tid] = att;
    __syncthreads();
    if (tid < 64) {
        float a = sacc[tid] + sacc[tid + 64];
        float at = satt[0] + satt[64];
        float cnt = (float)(e - s);
        float gat = (at == 0.f) ? 1.f : at;
        float scale = cnt / (gat * fmaxf(cnt, 1.f));
        sx[tid] = a * scale;
    }
    __syncthreads();
    float a = f1b[tid];
#pragma unroll 8
    for (int k = 0; k < 64; k++) a = fmaf(sx[k], f1w[k * 128 + tid], a);
    shh[tid] = fmaxf(a, 0.f);
    __syncthreads();
    if (tid < 3) {
        float o = f2b[tid];
        for (int j = 0; j < 128; j++) o = fmaf(shh[j], f2w[j * 3 + tid], o);
        out[g * 3 + tid] = o;
    }
}

// ---------------- launch ----------------
extern "C" void kernel_launch(void* const* d_in, const int* in_sizes, int n_in,
                              void* d_out, int out_size) {
    const float* x     = (const float*)d_in[0];
    const int*   ei    = (const int*)d_in[1];
    const int*   batch = (const int*)d_in[2];
    const float* eattr = (const float*)d_in[3];
    const float* eatt  = (const float*)d_in[4];
    const float* embw  = (const float*)d_in[5];
    const float* embb  = (const float*)d_in[6];
    const float* l1w   = (const float*)d_in[7];
    const float* l1b   = (const float*)d_in[8];
    const float* l2w   = (const float*)d_in[9];
    const float* l3w   = (const float*)d_in[10];
    const float* l3b   = (const float*)d_in[11];
    const float* f1w   = (const float*)d_in[12];
    const float* f1b   = (const float*)d_in[13];
    const float* f2w   = (const float*)d_in[14];
    const float* f2b   = (const float*)d_in[15];
    float* out = (float*)d_out;

    const int smem_gemm = (128 * 68 + 64 * 200) * 4;  // 86016 B
    cudaFuncSetAttribute(k_gemm, cudaFuncAttributeMaxDynamicSharedMemorySize, smem_gemm);

    const int* src = ei;
    const int* dst = ei + NE;

    k_init<<<(NN * 32 + 255) / 256, 256>>>(x, embw, embb);
    k_edge<<<(NE / 4 + 255) / 256, 256>>>(dst);
    k_scan<<<(NN + 1023) / 1024, 256>>>();
    k_fill<<<(NE / 4 + 255) / 256, 256>>>(src, dst, eattr, eatt);
    k_rowstats<<<(NN * 32 + 255) / 256, 256>>>();

    for (int l = 0; l < 3; l++) {
        k_gemm<<<(NN + 127) / 128, 256, smem_gemm>>>(
            l1w + l * 4096, l2w + l * 4096, l3w + l * 4096,
            l1b + l * 64, l3b + l * 64);
        k_gather<<<(NN * 32 + 255) / 256, 256>>>();
    }

    k_poolmlp<<<NGR, 128>>>(batch, f1w, f1b, f2w, f2b, out);
}

// round 10
// speedup vs baseline: 1.2801x; 1.0134x over previous
#include <cuda_runtime.h>
#include <cuda_fp16.h>
#include <cstdint>

#define NN 100000
#define NE 1000000
#define NGR 512

// ---------------- scratch ----------------
// NOTE: g_cnt/g_atts/g_degs/g_bsum/g_tick are zeroed at the TAIL of k_poolmlp
// (previous run) -- first run relies on static zero-init of device globals.
__device__ float g_Win[NN];       // sum of incoming edge weights (row sums)
__device__ float g_atts[NN];      // src-side attention sum (atomic)
__device__ int   g_degs[NN];      // src-side degree (atomic)
__device__ float g_natt[NN];      // final node attention
__device__ int   g_cnt[NN];       // in-degree (CSR row counts)
__device__ int   g_rs[NN];        // CSR row start
__device__ int   g_cur[NN];       // CSR fill cursor
__device__ int   g_bsum[128];     // chained-scan flags
__device__ int   g_tick;
__device__ float4 g_ce[NE];       // CSR: {src_as_bits, w, atten, pad}
__device__ __half g_hh[NN * 64];  // h in fp16
__device__ __half g_Ah[NN * 64];  // A in fp16
__device__ __half g_Dh[NN * 64];  // D in fp16

__device__ __forceinline__ uint32_t f2tf32(float f) {
    uint32_t o;
    asm("cvt.rna.tf32.f32 %0, %1;" : "=r"(o) : "f"(f));
    return o;
}

// ------- init: node embedding (h fp16) + dst in-degree histogram (fused) -----
__global__ void k_initedge(const float* __restrict__ x, const float* __restrict__ w,
                           const float* __restrict__ b, const int* __restrict__ dst) {
    int gid = blockIdx.x * 256 + threadIdx.x;
    if (gid < NE / 4) {
        int4 d = *(const int4*)&dst[gid * 4];
        atomicAdd(&g_cnt[d.x], 1); atomicAdd(&g_cnt[d.y], 1);
        atomicAdd(&g_cnt[d.z], 1); atomicAdd(&g_cnt[d.w], 1);
    }
    if (gid < NN * 32) {
        int i = gid >> 5, c = (gid & 31) * 2;
        float4 xv = *(const float4*)&x[i * 4];
        float h0 = b[c]     + xv.x * w[c]     + xv.y * w[64 + c]     + xv.z * w[128 + c]     + xv.w * w[192 + c];
        float h1 = b[c + 1] + xv.x * w[c + 1] + xv.y * w[64 + c + 1] + xv.z * w[128 + c + 1] + xv.w * w[192 + c + 1];
        *(__half2*)&g_hh[i * 64 + c] = __floats2half2_rn(h0, h1);
    }
}

// ---------------- single-pass chained exclusive scan: g_cnt -> g_rs, g_cur ----
__global__ void k_scan() {
    __shared__ int sm_t, sm_prev, wsum[8];
    int tid = threadIdx.x;
    if (tid == 0) sm_t = atomicAdd(&g_tick, 1);
    __syncthreads();
    int t = sm_t;
    int base = t * 1024 + tid * 4;
    int v0 = 0, v1 = 0, v2 = 0, v3 = 0;
    if (base + 3 < NN) {
        int4 q = *(const int4*)&g_cnt[base];
        v0 = q.x; v1 = q.y; v2 = q.z; v3 = q.w;
    } else {
        if (base < NN)     v0 = g_cnt[base];
        if (base + 1 < NN) v1 = g_cnt[base + 1];
        if (base + 2 < NN) v2 = g_cnt[base + 2];
        if (base + 3 < NN) v3 = g_cnt[base + 3];
    }
    int sloc = v0 + v1 + v2 + v3;
    int x = sloc;
#pragma unroll
    for (int o = 1; o < 32; o <<= 1) {
        int y = __shfl_up_sync(0xffffffffu, x, o);
        if ((tid & 31) >= o) x += y;
    }
    if ((tid & 31) == 31) wsum[tid >> 5] = x;
    __syncthreads();
    if (tid < 8) {
        int y = wsum[tid];
#pragma unroll
        for (int o = 1; o < 8; o <<= 1) {
            int z = __shfl_up_sync(0xffu, y, o);
            if (tid >= o) y += z;
        }
        wsum[tid] = y;
    }
    __syncthreads();
    int woff = (tid >= 32) ? wsum[(tid >> 5) - 1] : 0;
    int excl = x - sloc + woff;
    int total = wsum[7];
    if (tid == 0) {
        int prev = 0;
        if (t > 0) {
            int v;
            while ((v = atomicAdd(&g_bsum[t - 1], 0)) == 0) {}
            prev = v - 1;
        }
        atomicExch(&g_bsum[t], prev + total + 1);
        sm_prev = prev;
    }
    __syncthreads();
    int off = sm_prev + excl;
    if (base < NN)     { g_rs[base]     = off;                g_cur[base]     = off; }
    if (base + 1 < NN) { g_rs[base + 1] = off + v0;           g_cur[base + 1] = off + v0; }
    if (base + 2 < NN) { g_rs[base + 2] = off + v0 + v1;      g_cur[base + 2] = off + v0 + v1; }
    if (base + 3 < NN) { g_rs[base + 3] = off + v0 + v1 + v2; g_cur[base + 3] = off + v0 + v1 + v2; }
}

// ---------------- CSR fill + src-side atomics (4 edges/thread, 16B records) --
__global__ void k_fill(const int* __restrict__ src, const int* __restrict__ dst,
                       const float* __restrict__ attr, const float* __restrict__ atten) {
    int e4 = blockIdx.x * 256 + threadIdx.x;
    if (e4 * 4 >= NE) return;
    int4 s = *(const int4*)&src[e4 * 4];
    int4 d = *(const int4*)&dst[e4 * 4];
    float4 ar = *(const float4*)&attr[e4 * 4];
    float4 at = *(const float4*)&atten[e4 * 4];
    int p0 = atomicAdd(&g_cur[d.x], 1);
    int p1 = atomicAdd(&g_cur[d.y], 1);
    int p2 = atomicAdd(&g_cur[d.z], 1);
    int p3 = atomicAdd(&g_cur[d.w], 1);
    g_ce[p0] = make_float4(__int_as_float(s.x), ar.x * at.x, at.x, 0.f);
    g_ce[p1] = make_float4(__int_as_float(s.y), ar.y * at.y, at.y, 0.f);
    g_ce[p2] = make_float4(__int_as_float(s.z), ar.z * at.z, at.z, 0.f);
    g_ce[p3] = make_float4(__int_as_float(s.w), ar.w * at.w, at.w, 0.f);
    atomicAdd(&g_atts[s.x], at.x); atomicAdd(&g_atts[s.y], at.y);
    atomicAdd(&g_atts[s.z], at.z); atomicAdd(&g_atts[s.w], at.w);
    atomicAdd(&g_degs[s.x], 1);    atomicAdd(&g_degs[s.y], 1);
    atomicAdd(&g_degs[s.z], 1);    atomicAdd(&g_degs[s.w], 1);
}

// ---------------- row stats: Win, natt (warp per node, sequential reads) -----
__global__ void k_rowstats() {
    int gt = blockIdx.x * 256 + threadIdx.x;
    int node = gt >> 5, lane = gt & 31;
    if (node >= NN) return;
    int s = g_rs[node];
    int len = g_cnt[node];
    float wsum = 0.f, asum = 0.f;
    for (int i = lane; i < len; i += 32) {
        float4 ce = g_ce[s + i];
        wsum += ce.y;
        asum += ce.z;
    }
#pragma unroll
    for (int o = 16; o > 0; o >>= 1) {
        wsum += __shfl_down_sync(0xffffffffu, wsum, o);
        asum += __shfl_down_sync(0xffffffffu, asum, o);
    }
    if (lane == 0) {
        g_Win[node] = wsum;
        float att_tot = asum + g_atts[node];
        float deg = (float)(len + g_degs[node]);
        g_natt[node] = att_tot / ((deg == 0.f) ? 1.f : deg);
    }
}

// ---------------- layer GEMM via mma.sync tf32 (h fp16 in, A/D fp16 out) -----
__global__ void __launch_bounds__(256, 2) k_gemm(const float* __restrict__ W1,
                                                 const float* __restrict__ W2,
                                                 const float* __restrict__ W3,
                                                 const float* __restrict__ b1,
                                                 const float* __restrict__ b3) {
    extern __shared__ float sm[];
    float* sh_h = sm;              // [128][68] tf32 words
    float* sh_w = sm + 128 * 68;   // [64][200]
    int tid = threadIdx.x;
    int nbase = blockIdx.x * 128;

    for (int i = tid; i < 1024; i += 256) {
        int node = i >> 3, k8 = (i & 7) << 3;
        int gn = nbase + node;
        uint4 v = make_uint4(0u, 0u, 0u, 0u);
        if (gn < NN) v = *(const uint4*)&g_hh[gn * 64 + k8];
        __half2* hv = (__half2*)&v;
        uint32_t* p = (uint32_t*)&sh_h[node * 68 + k8];
#pragma unroll
        for (int j = 0; j < 4; j++) {
            float2 f = __half22float2(hv[j]);
            p[2 * j] = f2tf32(f.x); p[2 * j + 1] = f2tf32(f.y);
        }
    }
    for (int i = tid; i < 3072; i += 256) {
        int row = i / 48;
        int q = i % 48;
        int m = q >> 4, c4 = (q & 15) << 2;
        const float* Wm = (m == 0) ? W1 : ((m == 1) ? W2 : W3);
        float4 v = *(const float4*)&Wm[row * 64 + c4];
        uint32_t* p = (uint32_t*)&sh_w[row * 200 + m * 64 + c4];
        p[0] = f2tf32(v.x); p[1] = f2tf32(v.y); p[2] = f2tf32(v.z); p[3] = f2tf32(v.w);
    }
    __syncthreads();

    int w = tid >> 5, lane = tid & 31;
    int rowG = w & 3, colH = w >> 2;
    int gid = lane >> 2, tid4 = lane & 3;

    float acc[24][4];
#pragma unroll
    for (int t = 0; t < 24; t++) {
        acc[t][0] = 0.f; acc[t][1] = 0.f; acc[t][2] = 0.f; acc[t][3] = 0.f;
    }

    const uint32_t* hp = (const uint32_t*)(sh_h + rowG * 32 * 68);
    const uint32_t* wp = (const uint32_t*)sh_w;

#pragma unroll
    for (int kt = 0; kt < 8; kt++) {
        int k0 = kt * 8;
        uint32_t a[2][4];
#pragma unroll
        for (int rt = 0; rt < 2; rt++) {
            const uint32_t* hq = hp + rt * 16 * 68;
            a[rt][0] = hq[gid * 68 + k0 + tid4];
            a[rt][1] = hq[(gid + 8) * 68 + k0 + tid4];
            a[rt][2] = hq[gid * 68 + k0 + tid4 + 4];
            a[rt][3] = hq[(gid + 8) * 68 + k0 + tid4 + 4];
        }
#pragma unroll
        for (int m = 0; m < 3; m++) {
#pragma unroll
            for (int tt = 0; tt < 4; tt++) {
                int nb = m * 64 + colH * 32 + tt * 8;
                uint32_t bb0 = wp[(k0 + tid4) * 200 + nb + gid];
                uint32_t bb1 = wp[(k0 + tid4 + 4) * 200 + nb + gid];
#pragma unroll
                for (int rt = 0; rt < 2; rt++) {
                    float* c = acc[rt * 12 + m * 4 + tt];
                    asm volatile(
                        "mma.sync.aligned.m16n8k8.row.col.f32.tf32.tf32.f32 "
                        "{%0,%1,%2,%3}, {%4,%5,%6,%7}, {%8,%9}, {%0,%1,%2,%3};"
                        : "+f"(c[0]), "+f"(c[1]), "+f"(c[2]), "+f"(c[3])
                        : "r"(a[rt][0]), "r"(a[rt][1]), "r"(a[rt][2]), "r"(a[rt][3]),
                          "r"(bb0), "r"(bb1));
                }
            }
        }
    }

#pragma unroll
    for (int rt = 0; rt < 2; rt++) {
        int r1 = nbase + rowG * 32 + rt * 16 + gid;
        int r2 = r1 + 8;
        float win1 = (r1 < NN) ? g_Win[r1] : 0.f;
        float win2 = (r2 < NN) ? g_Win[r2] : 0.f;
#pragma unroll
        for (int tt = 0; tt < 4; tt++) {
            int c = colH * 32 + tt * 8 + tid4 * 2;
            float2 b1v = *(const float2*)&b1[c];
            float2 b3v = *(const float2*)&b3[c];
            float* aW1 = acc[rt * 12 + tt];
            float* aW2 = acc[rt * 12 + 4 + tt];
            float* aW3 = acc[rt * 12 + 8 + tt];
            if (r1 < NN) {
                *(__half2*)&g_Ah[r1 * 64 + c] =
                    __floats2half2_rn(aW1[0] + b1v.x, aW1[1] + b1v.y);
                *(__half2*)&g_Dh[r1 * 64 + c] =
                    __floats2half2_rn(aW3[0] + b3v.x - win1 * aW2[0],
                                      aW3[1] + b3v.y - win1 * aW2[1]);
            }
            if (r2 < NN) {
                *(__half2*)&g_Ah[r2 * 64 + c] =
                    __floats2half2_rn(aW1[2] + b1v.x, aW1[3] + b1v.y);
                *(__half2*)&g_Dh[r2 * 64 + c] =
                    __floats2half2_rn(aW3[2] + b3v.x - win2 * aW2[2],
                                      aW3[3] + b3v.y - win2 * aW2[3]);
            }
        }
    }
}

// ---------------- gather: h = relu( sum_e w*A[src] + D ), warp per node ------
__global__ void k_gather() {
    int gt = blockIdx.x * 256 + threadIdx.x;
    int node = gt >> 5, lane = gt & 31;
    if (node >= NN) return;
    int s = g_rs[node];
    int e = s + g_cnt[node];
    int loff = lane * 2;
    float ax0 = 0.f, ay0 = 0.f, ax1 = 0.f, ay1 = 0.f;
    for (int base = s; base < e; base += 32) {
        int idx = base + lane;
        float4 ce = make_float4(0.f, 0.f, 0.f, 0.f);
        if (idx < e) ce = g_ce[idx];
        int sn = __float_as_int(ce.x);
        float wv = ce.y;
        int m = min(32, e - base);
        int mr = (m + 3) & ~3;
        for (int j = 0; j < mr; j += 4) {
            int s0 = __shfl_sync(0xffffffffu, sn, j);
            int s1 = __shfl_sync(0xffffffffu, sn, j + 1);
            int s2 = __shfl_sync(0xffffffffu, sn, j + 2);
            int s3 = __shfl_sync(0xffffffffu, sn, j + 3);
            float w0 = __shfl_sync(0xffffffffu, wv, j);
            float w1 = __shfl_sync(0xffffffffu, wv, j + 1);
            float w2 = __shfl_sync(0xffffffffu, wv, j + 2);
            float w3 = __shfl_sync(0xffffffffu, wv, j + 3);
            __half2 h0 = __ldg((const __half2*)&g_Ah[s0 * 64 + loff]);
            __half2 h1 = __ldg((const __half2*)&g_Ah[s1 * 64 + loff]);
            __half2 h2 = __ldg((const __half2*)&g_Ah[s2 * 64 + loff]);
            __half2 h3 = __ldg((const __half2*)&g_Ah[s3 * 64 + loff]);
            float2 v0 = __half22float2(h0);
            float2 v1 = __half22float2(h1);
            float2 v2 = __half22float2(h2);
            float2 v3 = __half22float2(h3);
            ax0 = fmaf(w0, v0.x, ax0); ay0 = fmaf(w0, v0.y, ay0);
            ax1 = fmaf(w1, v1.x, ax1); ay1 = fmaf(w1, v1.y, ay1);
            ax0 = fmaf(w2, v2.x, ax0); ay0 = fmaf(w2, v2.y, ay0);
            ax1 = fmaf(w3, v3.x, ax1); ay1 = fmaf(w3, v3.y, ay1);
        }
    }
    float2 dv = __half22float2(*(const __half2*)&g_Dh[node * 64 + loff]);
    *(__half2*)&g_hh[node * 64 + loff] =
        __floats2half2_rn(fmaxf(ax0 + ax1 + dv.x, 0.f), fmaxf(ay0 + ay1 + dv.y, 0.f));
}

// ------- fused pooling + MLP + scratch re-zero for next replay ---------------
__global__ void k_poolmlp(const int* __restrict__ batch,
                          const float* __restrict__ f1w, const float* __restrict__ f1b,
                          const float* __restrict__ f2w, const float* __restrict__ f2b,
                          float* __restrict__ out) {
    int g = blockIdx.x, tid = threadIdx.x;  // 128
    __shared__ int se[2];
    __shared__ float sacc[128], satt[128];
    __shared__ float sx[64], shh[128];

    // cleanup for next run (all readers of these arrays already finished)
    int tg = g * 128 + tid;  // 0..65535
    for (int i = tg; i < NN; i += NGR * 128) {
        g_cnt[i] = 0; g_atts[i] = 0.f; g_degs[i] = 0;
    }
    if (tg < 128) g_bsum[tg] = 0;
    if (tg == 0) g_tick = 0;

    if (tid < 2) {
        int key = g + tid;
        int lo = 0, hi = NN;
        while (lo < hi) {
            int mid = (lo + hi) >> 1;
            if (batch[mid] < key) lo = mid + 1; else hi = mid;
        }
        se[tid] = lo;
    }
    __syncthreads();
    int s = se[0], e = se[1];
    int c = tid & 63, part = tid >> 6;
    float acc = 0.f, att = 0.f;
    for (int i = s + part; i < e; i += 2) {
        float na = g_natt[i];
        acc = fmaf(__half2float(g_hh[i * 64 + c]), na, acc);
        att += na;
    }
    sacc[tid] = acc; satt[tid] = att;
    __syncthreads();
    if (tid < 64) {
        float a = sacc[tid] + sacc[tid + 64];
        float at = satt[0] + satt[64];
        float cnt = (float)(e - s);
        float gat = (at == 0.f) ? 1.f : at;
        float scale = cnt / (gat * fmaxf(cnt, 1.f));
        sx[tid] = a * scale;
    }
    __syncthreads();
    float a = f1b[tid];
#pragma unroll 8
    for (int k = 0; k < 64; k++) a = fmaf(sx[k], f1w[k * 128 + tid], a);
    shh[tid] = fmaxf(a, 0.f);
    __syncthreads();
    if (tid < 3) {
        float o = f2b[tid];
        for (int j = 0; j < 128; j++) o = fmaf(shh[j], f2w[j * 3 + tid], o);
        out[g * 3 + tid] = o;
    }
}

// ---------------- launch ----------------
extern "C" void kernel_launch(void* const* d_in, const int* in_sizes, int n_in,
                              void* d_out, int out_size) {
    const float* x     = (const float*)d_in[0];
    const int*   ei    = (const int*)d_in[1];
    const int*   batch = (const int*)d_in[2];
    const float* eattr = (const float*)d_in[3];
    const float* eatt  = (const float*)d_in[4];
    const float* embw  = (const float*)d_in[5];
    const float* embb  = (const float*)d_in[6];
    const float* l1w   = (const float*)d_in[7];
    const float* l1b   = (const float*)d_in[8];
    const float* l2w   = (const float*)d_in[9];
    const float* l3w   = (const float*)d_in[10];
    const float* l3b   = (const float*)d_in[11];
    const float* f1w   = (const float*)d_in[12];
    const float* f1b   = (const float*)d_in[13];
    const float* f2w   = (const float*)d_in[14];
    const float* f2b   = (const float*)d_in[15];
    float* out = (float*)d_out;

    const int smem_gemm = (128 * 68 + 64 * 200) * 4;  // 86016 B
    cudaFuncSetAttribute(k_gemm, cudaFuncAttributeMaxDynamicSharedMemorySize, smem_gemm);

    const int* src = ei;
    const int* dst = ei + NE;

    k_initedge<<<(NN * 32 + 255) / 256, 256>>>(x, embw, embb, dst);
    k_scan<<<(NN + 1023) / 1024, 256>>>();
    k_fill<<<(NE / 4 + 255) / 256, 256>>>(src, dst, eattr, eatt);
    k_rowstats<<<(NN * 32 + 255) / 256, 256>>>();

    for (int l = 0; l < 3; l++) {
        k_gemm<<<(NN + 127) / 128, 256, smem_gemm>>>(
            l1w + l * 4096, l2w + l * 4096, l3w + l * 4096,
            l1b + l * 64, l3b + l * 64);
        k_gather<<<(NN * 32 + 255) / 256, 256>>>();
    }

    k_poolmlp<<<NGR, 128>>>(batch, f1w, f1b, f2w, f2b, out);
}